// round 2
// baseline (speedup 1.0000x reference)
#include <cuda_runtime.h>
#include <math.h>

// PSRoIPool (R-FCN position-sensitive RoI pooling), 8 lanes per output element.
//   rois:     [N=128, 5]  (batch_idx, x1, y1, x2, y2)  float32
//   features: [B=2, C=392, H=50, W=84]                  float32
//   out:      [N, D=8, G=7, G=7]                        float32
//
// out[n,d,i,j] = sum_{bin pixels} feat[b, (d*G+i)*G+j, h, w] / area
// with R-FCN rounded-corner bin geometry (see reference).

#define G 7
#define LPG 8   // lanes per output group (must divide 32)

__global__ __launch_bounds__(256) void psroi_kernel8(
    const float* __restrict__ rois,
    const float* __restrict__ feat,
    float* __restrict__ out,
    float scale, int N, int D, int H, int W)
{
    int tid   = blockIdx.x * blockDim.x + threadIdx.x;
    int group = tid / LPG;          // output element index
    int lane  = tid % LPG;
    int total = N * D * G * G;
    if (group >= total) return;

    int j = group % G;
    int i = (group / G) % G;
    int d = (group / (G * G)) % D;
    int n = group / (D * G * G);

    const float* r = rois + n * 5;
    int   b  = (int)r[0];
    float xs = rintf(r[1]) * scale;
    float ys = rintf(r[2]) * scale;
    float xe = (rintf(r[3]) + 1.0f) * scale;
    float ye = (rintf(r[4]) + 1.0f) * scale;

    float bw = fmaxf(xe - xs, 0.1f) * (1.0f / (float)G);
    float bh = fmaxf(ye - ys, 0.1f) * (1.0f / (float)G);

    int ws = min(max((int)floorf((float)j * bw + xs), 0), W);
    int we = min(max((int)ceilf(((float)j + 1.0f) * bw + xs), 0), W);
    int hs = min(max((int)floorf((float)i * bh + ys), 0), H);
    int he = min(max((int)ceilf(((float)i + 1.0f) * bh + ys), 0), H);

    int bwc   = we - ws;                 // bin width in cols (may be <= 0)
    int bhc   = he - hs;
    int count = (bwc > 0 && bhc > 0) ? bwc * bhc : 0;
    float area = fmaxf((float)(bhc * bwc), 1.0f);

    int C = D * G * G;
    int c = (d * G + i) * G + j;
    const float* fp = feat + ((size_t)b * C + c) * (size_t)(H * W);

    float s = 0.0f;
    for (int p = lane; p < count; p += LPG) {
        int h = p / bwc;
        int w = p - h * bwc;
        s += __ldg(fp + (hs + h) * W + (ws + w));
    }

    // reduce within the aligned 8-lane group
    s += __shfl_xor_sync(0xffffffffu, s, 1);
    s += __shfl_xor_sync(0xffffffffu, s, 2);
    s += __shfl_xor_sync(0xffffffffu, s, 4);

    if (lane == 0) out[group] = s / area;
}

extern "C" void kernel_launch(void* const* d_in, const int* in_sizes, int n_in,
                              void* d_out, int out_size)
{
    const float* rois = (const float*)d_in[0];
    const float* feat = (const float*)d_in[1];
    (void)n_in;

    const int stride = 16;                  // scalar input, constant for this problem
    const int N = in_sizes[0] / 5;          // 128
    const int H = 50, W = 84;
    const int D = out_size / (N * G * G);   // 8

    float scale = 1.0f / (float)stride;

    int total   = N * D * G * G;            // 50176 outputs
    int threads = 256;
    int blocks  = (total * LPG + threads - 1) / threads;   // 1568
    psroi_kernel8<<<blocks, threads>>>(rois, feat, (float*)d_out, scale, N, D, H, W);
}

// round 3
// speedup vs baseline: 1.0993x; 1.0993x over previous
#include <cuda_runtime.h>
#include <math.h>

// PSRoIPool (R-FCN), d-vectorized: one block per roi, 49 bin-groups x 8 lanes.
//   rois:     [N=128, 5]  (batch_idx, x1, y1, x2, y2)  float32
//   features: [B=2, C=392, H=50, W=84]                  float32
//   out:      [N, D=8, G=7, G=7]                        float32
//
// Each 8-lane group handles one (i,j) bin and produces all 8 d outputs:
// lanes split the bin pixels, each pixel contributes 8 channel loads
// (channel = d*49 + i*7 + j, stride 49*H*W) -> MLP=8.

#define G   7
#define D   8
#define Hf  50
#define Wf  84
#define HW  (Hf * Wf)           // 4200
#define Cf  (D * G * G)         // 392
#define DSTRIDE (G * G * HW)    // 205800 floats between d-channels

__global__ __launch_bounds__(392) void psroi_dvec_kernel(
    const float* __restrict__ rois,
    const float* __restrict__ feat,
    float* __restrict__ out,
    float scale)
{
    __shared__ int s_hs[G], s_he[G], s_ws[G], s_we[G];
    __shared__ int s_b;

    const int n = blockIdx.x;
    const int t = threadIdx.x;

    // ---- geometry: computed once per roi by first 17 threads ----
    if (t < 17) {
        const float* r = rois + n * 5;
        if (t < G) {
            // h bounds for bin row i = t
            float ys = rintf(r[2]) * scale;
            float ye = (rintf(r[4]) + 1.0f) * scale;
            float bh = fmaxf(ye - ys, 0.1f) * (1.0f / (float)G);
            float hs = fminf(fmaxf(floorf((float)t * bh + ys), 0.0f), (float)Hf);
            float he = fminf(fmaxf(ceilf(((float)t + 1.0f) * bh + ys), 0.0f), (float)Hf);
            s_hs[t] = (int)hs;
            s_he[t] = (int)he;
        } else if (t >= 8 && t < 8 + G) {
            // w bounds for bin col j = t-8
            int j = t - 8;
            float xs = rintf(r[1]) * scale;
            float xe = (rintf(r[3]) + 1.0f) * scale;
            float bw = fmaxf(xe - xs, 0.1f) * (1.0f / (float)G);
            float ws = fminf(fmaxf(floorf((float)j * bw + xs), 0.0f), (float)Wf);
            float we = fminf(fmaxf(ceilf(((float)j + 1.0f) * bw + xs), 0.0f), (float)Wf);
            s_ws[j] = (int)ws;
            s_we[j] = (int)we;
        } else if (t == 16) {
            s_b = (int)r[0];
        }
    }
    __syncthreads();

    const int lane = t & 7;
    const int ij   = t >> 3;          // 0..48
    const int i    = ij / G;
    const int j    = ij - i * G;

    const int hs = s_hs[i], he = s_he[i];
    const int ws = s_ws[j], we = s_we[j];
    const int bwc = we - ws;
    const int bhc = he - hs;
    const int count = bhc * bwc;      // <=0 => empty bin
    const float area = fmaxf((float)count, 1.0f);

    const float* base = feat + ((size_t)s_b * Cf + i * G + j) * (size_t)HW;

    float acc[D];
    #pragma unroll
    for (int d = 0; d < D; ++d) acc[d] = 0.0f;

    for (int p = lane; p < count; p += 8) {
        unsigned h = (unsigned)p / (unsigned)bwc;
        unsigned w = (unsigned)p - h * (unsigned)bwc;
        const float* px = base + (hs + (int)h) * Wf + ws + (int)w;
        #pragma unroll
        for (int d = 0; d < D; ++d)
            acc[d] += __ldg(px + d * DSTRIDE);
    }

    // butterfly reduce within aligned 8-lane group
    #pragma unroll
    for (int d = 0; d < D; ++d) {
        acc[d] += __shfl_xor_sync(0xffffffffu, acc[d], 1);
        acc[d] += __shfl_xor_sync(0xffffffffu, acc[d], 2);
        acc[d] += __shfl_xor_sync(0xffffffffu, acc[d], 4);
    }

    // lane l writes output d = l:  out[n, d, i, j]
    out[(size_t)n * Cf + lane * (G * G) + ij] = acc[lane] / area;
}

extern "C" void kernel_launch(void* const* d_in, const int* in_sizes, int n_in,
                              void* d_out, int out_size)
{
    const float* rois = (const float*)d_in[0];
    const float* feat = (const float*)d_in[1];
    (void)n_in; (void)out_size;

    const int stride = 16;                 // scalar input, constant for this problem
    const int N = in_sizes[0] / 5;         // 128
    float scale = 1.0f / (float)stride;

    psroi_dvec_kernel<<<N, D * G * G>>>(rois, feat, (float*)d_out, scale);
}

// round 4
// speedup vs baseline: 1.1033x; 1.0037x over previous
#include <cuda_runtime.h>
#include <math.h>

// PSRoIPool (R-FCN), d-vectorized, 16 lanes per bin.
//   rois:     [N=128, 5]  (batch_idx, x1, y1, x2, y2)  float32
//   features: [B=2, C=392, H=50, W=84]                  float32
//   out:      [N, D=8, G=7, G=7]                        float32
//
// One block per roi: 49 bins x 16 lanes = 784 threads.
// Lanes split the bin's pixels 16-way; each pixel contributes 8 channel
// loads (channel = d*49 + i*7 + j, stride 49*H*W) -> MLP=8 per iteration.
// Butterfly-reduce over the 16-lane group; lanes 0..7 write d=lane.

#define G   7
#define D   8
#define Hf  50
#define Wf  84
#define HW  (Hf * Wf)           // 4200
#define Cf  (D * G * G)         // 392
#define DSTRIDE (G * G * HW)    // 205800 floats between d-channels
#define LPG 16                  // lanes per bin group

__global__ __launch_bounds__(G * G * LPG) void psroi_dvec16_kernel(
    const float* __restrict__ rois,
    const float* __restrict__ feat,
    float* __restrict__ out,
    float scale)
{
    __shared__ int s_hs[G], s_he[G], s_ws[G], s_we[G];
    __shared__ int s_b;

    const int n = blockIdx.x;
    const int t = threadIdx.x;

    // ---- geometry: computed once per roi by warp 0 ----
    if (t < 16) {
        const float* r = rois + n * 5;
        if (t < G) {
            float ys = rintf(r[2]) * scale;
            float ye = (rintf(r[4]) + 1.0f) * scale;
            float bh = fmaxf(ye - ys, 0.1f) * (1.0f / (float)G);
            s_hs[t] = (int)fminf(fmaxf(floorf((float)t * bh + ys), 0.0f), (float)Hf);
            s_he[t] = (int)fminf(fmaxf(ceilf(((float)t + 1.0f) * bh + ys), 0.0f), (float)Hf);
        } else if (t >= 8 && t < 8 + G) {
            int j = t - 8;
            float xs = rintf(r[1]) * scale;
            float xe = (rintf(r[3]) + 1.0f) * scale;
            float bw = fmaxf(xe - xs, 0.1f) * (1.0f / (float)G);
            s_ws[j] = (int)fminf(fmaxf(floorf((float)j * bw + xs), 0.0f), (float)Wf);
            s_we[j] = (int)fminf(fmaxf(ceilf(((float)j + 1.0f) * bw + xs), 0.0f), (float)Wf);
        } else if (t == 15) {
            s_b = (int)r[0];
        }
    }
    __syncthreads();

    const int lane = t & (LPG - 1);
    const int ij   = t >> 4;          // 0..48
    const int i    = ij / G;
    const int j    = ij - i * G;

    const int hs = s_hs[i], he = s_he[i];
    const int ws = s_ws[j], we = s_we[j];
    const int bwc = we - ws;
    const int bhc = he - hs;
    const int count = bhc * bwc;      // <=0 => empty bin
    const float area = fmaxf((float)count, 1.0f);

    const float* base = feat + ((size_t)s_b * Cf + i * G + j) * (size_t)HW;

    float acc[D];
    #pragma unroll
    for (int d = 0; d < D; ++d) acc[d] = 0.0f;

    for (int p = lane; p < count; p += LPG) {
        unsigned h = (unsigned)p / (unsigned)bwc;
        unsigned w = (unsigned)p - h * (unsigned)bwc;
        const float* px = base + (hs + (int)h) * Wf + ws + (int)w;
        #pragma unroll
        for (int d = 0; d < D; ++d)
            acc[d] += __ldg(px + d * DSTRIDE);
    }

    // butterfly reduce within aligned 16-lane group
    #pragma unroll
    for (int d = 0; d < D; ++d) {
        acc[d] += __shfl_xor_sync(0xffffffffu, acc[d], 1);
        acc[d] += __shfl_xor_sync(0xffffffffu, acc[d], 2);
        acc[d] += __shfl_xor_sync(0xffffffffu, acc[d], 4);
        acc[d] += __shfl_xor_sync(0xffffffffu, acc[d], 8);
    }

    // lanes 0..7 write output d = lane:  out[n, d, i, j]
    if (lane < D)
        out[(size_t)n * Cf + lane * (G * G) + ij] = acc[lane] / area;
}

extern "C" void kernel_launch(void* const* d_in, const int* in_sizes, int n_in,
                              void* d_out, int out_size)
{
    const float* rois = (const float*)d_in[0];
    const float* feat = (const float*)d_in[1];
    (void)n_in; (void)out_size;

    const int stride = 16;                 // scalar input, constant for this problem
    const int N = in_sizes[0] / 5;         // 128
    float scale = 1.0f / (float)stride;

    psroi_dvec16_kernel<<<N, G * G * LPG>>>(rois, feat, (float*)d_out, scale);
}

// round 5
// speedup vs baseline: 1.1157x; 1.0112x over previous
#include <cuda_runtime.h>
#include <math.h>

// PSRoIPool (R-FCN), d-vectorized, 16 lanes per bin, barrier-free.
//   rois:     [N=128, 5]  (batch_idx, x1, y1, x2, y2)  float32
//   features: [B=2, C=392, H=50, W=84]                  float32
//   out:      [N, D=8, G=7, G=7]                        float32
//
// One block per roi: 49 bins x 16 lanes = 784 threads. No smem, no barrier:
// each thread computes its own bin bounds (~20 warp-uniform-ish ALU ops;
// chip-wide issue cost ~130 cycles). Each pixel contributes 8 channel loads
// (channel = d*49 + i*7 + j, stride 49*H*W) -> MLP=8 per loop iteration.
// Reduce-scatter butterfly (8 shfls) leaves d = lane&7 on lanes 0..7.

#define G   7
#define D   8
#define Hf  50
#define Wf  84
#define HW  (Hf * Wf)           // 4200
#define Cf  (D * G * G)         // 392
#define DSTRIDE (G * G * HW)    // 205800 floats between d-channels
#define LPG 16                  // lanes per bin group

__global__ __launch_bounds__(G * G * LPG) void psroi_nb_kernel(
    const float* __restrict__ rois,
    const float* __restrict__ feat,
    float* __restrict__ out,
    float scale)
{
    const int n = blockIdx.x;
    const int t = threadIdx.x;

    const int lane = t & (LPG - 1);
    const int ij   = t >> 4;          // 0..48
    const int i    = ij / G;
    const int j    = ij - i * G;

    // ---- per-thread geometry (warp-uniform rois load, L1-resident) ----
    const float* r = rois + n * 5;
    const int   b  = (int)__ldg(r + 0);
    const float xs = rintf(__ldg(r + 1)) * scale;
    const float ys = rintf(__ldg(r + 2)) * scale;
    const float xe = (rintf(__ldg(r + 3)) + 1.0f) * scale;
    const float ye = (rintf(__ldg(r + 4)) + 1.0f) * scale;

    const float bw = fmaxf(xe - xs, 0.1f) * (1.0f / (float)G);
    const float bh = fmaxf(ye - ys, 0.1f) * (1.0f / (float)G);

    const int ws = (int)fminf(fmaxf(floorf((float)j * bw + xs), 0.0f), (float)Wf);
    const int we = (int)fminf(fmaxf(ceilf(((float)j + 1.0f) * bw + xs), 0.0f), (float)Wf);
    const int hs = (int)fminf(fmaxf(floorf((float)i * bh + ys), 0.0f), (float)Hf);
    const int he = (int)fminf(fmaxf(ceilf(((float)i + 1.0f) * bh + ys), 0.0f), (float)Hf);

    const int bwc   = we - ws;        // >= 0 by construction
    const int bhc   = he - hs;
    const int count = bhc * bwc;
    const float area = fmaxf((float)count, 1.0f);

    const float* base = feat + ((size_t)b * Cf + i * G + j) * (size_t)HW;

    float acc[D];
    #pragma unroll
    for (int d = 0; d < D; ++d) acc[d] = 0.0f;

    for (int p = lane; p < count; p += LPG) {
        unsigned h = (unsigned)p / (unsigned)bwc;
        unsigned w = (unsigned)p - h * (unsigned)bwc;
        const float* px = base + (hs + (int)h) * Wf + ws + (int)w;
        #pragma unroll
        for (int d = 0; d < D; ++d)
            acc[d] += __ldg(px + d * DSTRIDE);
    }

    // ---- reduce-scatter butterfly over the 16-lane group ----
    // exact member mask for this group (lanes 0-15 or 16-31 of the warp)
    const unsigned gmask = 0xFFFFu << ((t & 31) & 16);
    const int b0 = lane & 1, b1 = (lane >> 1) & 1, b2 = (lane >> 2) & 1;

    // level 1 (mask 1): keep d with bit0(d)==b0          -> 4 values
    float v1[4];
    #pragma unroll
    for (int k = 0; k < 4; ++k) {
        float keep = b0 ? acc[2 * k + 1] : acc[2 * k];
        float send = b0 ? acc[2 * k]     : acc[2 * k + 1];
        v1[k] = keep + __shfl_xor_sync(gmask, send, 1);
    }
    // level 2 (mask 2): keep k with bit0(k)==b1          -> 2 values
    float v2[2];
    #pragma unroll
    for (int m = 0; m < 2; ++m) {
        float keep = b1 ? v1[2 * m + 1] : v1[2 * m];
        float send = b1 ? v1[2 * m]     : v1[2 * m + 1];
        v2[m] = keep + __shfl_xor_sync(gmask, send, 2);
    }
    // level 3 (mask 4): keep m==b2                        -> 1 value, d = lane&7
    {
        float keep = b2 ? v2[1] : v2[0];
        float send = b2 ? v2[0] : v2[1];
        v2[0] = keep + __shfl_xor_sync(gmask, send, 4);
    }
    // level 4 (mask 8): fold upper/lower 8-lane halves
    float v = v2[0] + __shfl_xor_sync(gmask, v2[0], 8);

    // lanes 0..7 of the group write output d = lane:  out[n, d, i, j]
    if (lane < D)
        out[(size_t)n * Cf + lane * (G * G) + ij] = v / area;
}

extern "C" void kernel_launch(void* const* d_in, const int* in_sizes, int n_in,
                              void* d_out, int out_size)
{
    const float* rois = (const float*)d_in[0];
    const float* feat = (const float*)d_in[1];
    (void)n_in; (void)out_size;

    const int stride = 16;                 // scalar input, constant for this problem
    const int N = in_sizes[0] / 5;         // 128
    float scale = 1.0f / (float)stride;

    psroi_nb_kernel<<<N, G * G * LPG>>>(rois, feat, (float*)d_out, scale);
}

// round 6
// speedup vs baseline: 1.2305x; 1.1029x over previous
#include <cuda_runtime.h>
#include <math.h>

// PSRoIPool (R-FCN), d-vectorized, 16 lanes per bin, one bin-ROW per block.
//   rois:     [N=128, 5]  (batch_idx, x1, y1, x2, y2)  float32
//   features: [B=2, C=392, H=50, W=84]                  float32
//   out:      [N, D=8, G=7, G=7]                        float32
//
// Grid (7, N): block (i, n) handles bin row i of roi n with 7 bins x 16
// lanes = 112 threads. Lanes tile the bin 8-wide (w) x 2-high (h) — no
// integer division in the loop, and the 8 w-lanes read one contiguous 32B
// sector per d-channel. Each pixel contributes 8 channel loads
// (channel = d*49 + i*7 + j, stride 49*H*W) -> MLP=8 per iteration.
// Reduce-scatter butterfly (8 shfls) leaves d = lane&7 on lanes 0..7.

#define G   7
#define D   8
#define Hf  50
#define Wf  84
#define HW  (Hf * Wf)           // 4200
#define Cf  (D * G * G)         // 392
#define DSTRIDE (G * G * HW)    // 205800 floats between d-channels
#define LPG 16                  // lanes per bin group

__global__ __launch_bounds__(G * LPG) void psroi_row_kernel(
    const float* __restrict__ rois,
    const float* __restrict__ feat,
    float* __restrict__ out,
    float scale)
{
    const int i = blockIdx.x;         // bin row 0..6
    const int n = blockIdx.y;         // roi
    const int t = threadIdx.x;        // 0..111

    const int lane = t & (LPG - 1);
    const int j    = t >> 4;          // bin col 0..6

    // ---- per-thread geometry (warp-uniform rois load, L1-resident) ----
    const float* r = rois + n * 5;
    const int   b  = (int)__ldg(r + 0);
    const float xs = rintf(__ldg(r + 1)) * scale;
    const float ys = rintf(__ldg(r + 2)) * scale;
    const float xe = (rintf(__ldg(r + 3)) + 1.0f) * scale;
    const float ye = (rintf(__ldg(r + 4)) + 1.0f) * scale;

    const float bw = fmaxf(xe - xs, 0.1f) * (1.0f / (float)G);
    const float bh = fmaxf(ye - ys, 0.1f) * (1.0f / (float)G);

    const int ws = (int)fminf(fmaxf(floorf((float)j * bw + xs), 0.0f), (float)Wf);
    const int we = (int)fminf(fmaxf(ceilf(((float)j + 1.0f) * bw + xs), 0.0f), (float)Wf);
    const int hs = (int)fminf(fmaxf(floorf((float)i * bh + ys), 0.0f), (float)Hf);
    const int he = (int)fminf(fmaxf(ceilf(((float)i + 1.0f) * bh + ys), 0.0f), (float)Hf);

    const int bwc = we - ws;          // >= 0 by construction
    const int bhc = he - hs;
    const float area = fmaxf((float)(bhc * bwc), 1.0f);

    const float* base = feat + ((size_t)b * Cf + i * G + j) * (size_t)HW;

    float acc[D];
    #pragma unroll
    for (int d = 0; d < D; ++d) acc[d] = 0.0f;

    // 2D-strided pixel loop: 8 lanes across w, 2 across h. No integer div.
    for (int hh = hs + (lane >> 3); hh < he; hh += 2) {
        const float* rowp = base + hh * Wf;
        for (int ww = ws + (lane & 7); ww < we; ww += 8) {
            #pragma unroll
            for (int d = 0; d < D; ++d)
                acc[d] += __ldg(rowp + ww + d * DSTRIDE);
        }
    }

    // ---- reduce-scatter butterfly over the 16-lane group ----
    const unsigned gmask = 0xFFFFu << (t & 16);   // exact member mask
    const int b0 = lane & 1, b1 = (lane >> 1) & 1, b2 = (lane >> 2) & 1;

    // level 1 (xor 1): keep d with bit0(d)==b0           -> 4 values
    float v1[4];
    #pragma unroll
    for (int k = 0; k < 4; ++k) {
        float keep = b0 ? acc[2 * k + 1] : acc[2 * k];
        float send = b0 ? acc[2 * k]     : acc[2 * k + 1];
        v1[k] = keep + __shfl_xor_sync(gmask, send, 1);
    }
    // level 2 (xor 2): keep k with bit0(k)==b1           -> 2 values
    float v2[2];
    #pragma unroll
    for (int m = 0; m < 2; ++m) {
        float keep = b1 ? v1[2 * m + 1] : v1[2 * m];
        float send = b1 ? v1[2 * m]     : v1[2 * m + 1];
        v2[m] = keep + __shfl_xor_sync(gmask, send, 2);
    }
    // level 3 (xor 4): keep m==b2                         -> 1 value, d = lane&7
    {
        float keep = b2 ? v2[1] : v2[0];
        float send = b2 ? v2[0] : v2[1];
        v2[0] = keep + __shfl_xor_sync(gmask, send, 4);
    }
    // level 4 (xor 8): fold the two 8-lane halves
    float v = v2[0] + __shfl_xor_sync(gmask, v2[0], 8);

    // lanes 0..7 write output d = lane:  out[n, d, i, j]
    if (lane < D)
        out[(size_t)n * Cf + lane * (G * G) + i * G + j] = __fdividef(v, area);
}

extern "C" void kernel_launch(void* const* d_in, const int* in_sizes, int n_in,
                              void* d_out, int out_size)
{
    const float* rois = (const float*)d_in[0];
    const float* feat = (const float*)d_in[1];
    (void)n_in; (void)out_size;

    const int stride = 16;                 // scalar input, constant for this problem
    const int N = in_sizes[0] / 5;         // 128
    float scale = 1.0f / (float)stride;

    dim3 grid(G, N);                       // (7, 128) = 896 blocks
    psroi_row_kernel<<<grid, G * LPG>>>(rois, feat, (float*)d_out, scale);
}

// round 7
// speedup vs baseline: 1.4444x; 1.1739x over previous
#include <cuda_runtime.h>
#include <math.h>

// PSRoIPool (R-FCN), d-vectorized, ONE WARP per bin, one bin-row per block.
//   rois:     [N=128, 5]  (batch_idx, x1, y1, x2, y2)  float32
//   features: [B=2, C=392, H=50, W=84]                  float32
//   out:      [N, D=8, G=7, G=7]                        float32
//
// Grid (7, N): block (i, n) handles bin row i of roi n with 7 bins x 32
// lanes = 224 threads. Each warp owns one (i,j) bin; lanes tile the bin
// 8-wide (w) x 4-high (h) — no integer division, and the 8 w-lanes read a
// contiguous 32B sector per d-channel. Each pixel contributes 8 channel
// loads (channel = d*49 + i*7 + j, stride 49*H*W) -> MLP=8 per iteration.
// 5-level reduce-scatter butterfly leaves d = lane&7 on lanes 0..7.

#define G   7
#define D   8
#define Hf  50
#define Wf  84
#define HW  (Hf * Wf)           // 4200
#define Cf  (D * G * G)         // 392
#define DSTRIDE (G * G * HW)    // 205800 floats between d-channels

__global__ __launch_bounds__(G * 32) void psroi_warp_kernel(
    const float* __restrict__ rois,
    const float* __restrict__ feat,
    float* __restrict__ out,
    float scale)
{
    const int i = blockIdx.x;         // bin row 0..6
    const int n = blockIdx.y;         // roi
    const int t = threadIdx.x;        // 0..223

    const int lane = t & 31;
    const int j    = t >> 5;          // bin col 0..6 (one warp per bin)

    // ---- per-thread geometry (warp-uniform rois load, L1-resident) ----
    const float* r = rois + n * 5;
    const int   b  = (int)__ldg(r + 0);
    const float xs = rintf(__ldg(r + 1)) * scale;
    const float ys = rintf(__ldg(r + 2)) * scale;
    const float xe = (rintf(__ldg(r + 3)) + 1.0f) * scale;
    const float ye = (rintf(__ldg(r + 4)) + 1.0f) * scale;

    const float bw = fmaxf(xe - xs, 0.1f) * (1.0f / (float)G);
    const float bh = fmaxf(ye - ys, 0.1f) * (1.0f / (float)G);

    const int ws = (int)fminf(fmaxf(floorf((float)j * bw + xs), 0.0f), (float)Wf);
    const int we = (int)fminf(fmaxf(ceilf(((float)j + 1.0f) * bw + xs), 0.0f), (float)Wf);
    const int hs = (int)fminf(fmaxf(floorf((float)i * bh + ys), 0.0f), (float)Hf);
    const int he = (int)fminf(fmaxf(ceilf(((float)i + 1.0f) * bh + ys), 0.0f), (float)Hf);

    const int bwc = we - ws;          // >= 0 by construction
    const int bhc = he - hs;
    const float area = fmaxf((float)(bhc * bwc), 1.0f);

    const float* base = feat + ((size_t)b * Cf + i * G + j) * (size_t)HW;

    float acc[D];
    #pragma unroll
    for (int d = 0; d < D; ++d) acc[d] = 0.0f;

    // 2D-strided pixel loop: 8 lanes across w, 4 across h. No integer div.
    for (int hh = hs + (lane >> 3); hh < he; hh += 4) {
        const float* rowp = base + hh * Wf;
        for (int ww = ws + (lane & 7); ww < we; ww += 8) {
            #pragma unroll
            for (int d = 0; d < D; ++d)
                acc[d] += __ldg(rowp + ww + d * DSTRIDE);
        }
    }

    // ---- reduce-scatter butterfly over the full warp ----
    const unsigned gmask = 0xFFFFFFFFu;
    const int b0 = lane & 1, b1 = (lane >> 1) & 1, b2 = (lane >> 2) & 1;

    // level 1 (xor 1): keep d with bit0(d)==b0           -> 4 values
    float v1[4];
    #pragma unroll
    for (int k = 0; k < 4; ++k) {
        float keep = b0 ? acc[2 * k + 1] : acc[2 * k];
        float send = b0 ? acc[2 * k]     : acc[2 * k + 1];
        v1[k] = keep + __shfl_xor_sync(gmask, send, 1);
    }
    // level 2 (xor 2): keep k with bit0(k)==b1           -> 2 values
    float v2[2];
    #pragma unroll
    for (int m = 0; m < 2; ++m) {
        float keep = b1 ? v1[2 * m + 1] : v1[2 * m];
        float send = b1 ? v1[2 * m]     : v1[2 * m + 1];
        v2[m] = keep + __shfl_xor_sync(gmask, send, 2);
    }
    // level 3 (xor 4): keep m==b2                         -> 1 value, d = lane&7
    float v;
    {
        float keep = b2 ? v2[1] : v2[0];
        float send = b2 ? v2[0] : v2[1];
        v = keep + __shfl_xor_sync(gmask, send, 4);
    }
    // levels 4,5 (xor 8, xor 16): fold the four 8-lane replicas
    v += __shfl_xor_sync(gmask, v, 8);
    v += __shfl_xor_sync(gmask, v, 16);

    // lanes 0..7 write output d = lane:  out[n, d, i, j]
    if (lane < D)
        out[(size_t)n * Cf + lane * (G * G) + i * G + j] = __fdividef(v, area);
}

extern "C" void kernel_launch(void* const* d_in, const int* in_sizes, int n_in,
                              void* d_out, int out_size)
{
    const float* rois = (const float*)d_in[0];
    const float* feat = (const float*)d_in[1];
    (void)n_in; (void)out_size;

    const int stride = 16;                 // scalar input, constant for this problem
    const int N = in_sizes[0] / 5;         // 128
    float scale = 1.0f / (float)stride;

    dim3 grid(G, N);                       // (7, 128) = 896 blocks
    psroi_warp_kernel<<<grid, G * 32>>>(rois, feat, (float*)d_out, scale);
}